// round 15
// baseline (speedup 1.0000x reference)
#include <cuda_runtime.h>
#include <cuda_bf16.h>

// BumpX: out[b,l,f] = sum_g mask(g-f, aa[b,l,f]) * x[b,l,g] / sum_g mask(...)
// mask(d,a) = 1 - gg(arg), arg = (d^2 - a^2)/(6a+9).
//
// Round 15: shortest-chain variant. The 8 window masks are per-d functions
// mask_d(a) on a in [0,1); each parity half's 4 masks are evaluated as TWO
// packed f32x2 Horner chains of degree 8 in s = 2a-1 (PTX fma.rn.f32x2),
// coefficients compile-time Chebyshev-interpolated from the EXACT reference
// formula (constexpr double, clamps included) and pair-packed per (h,chain).
// This removes from the critical path: rcp(6a+9) MUFU, a^2/c0/z setup, all
// four MUFU.TANH, and the mask-from-tanh FMAs. Chain: load a -> s -> pack ->
// 8 FFMA2 -> unpack -> accumulate.
//   * deg-10 per-d polys measured rel_err 1.5e-7 (R10); deg-8 lands ~1e-5
//     -> far inside the 1e-3 gate.  d=0's 0.5 double-count weight is baked
//     into its coefficients.
//   * |d|<=7 window: dropped taps have mask <= 4e-11 (numerically identical
//     to dense fp32).
// Structure (R12): warp owns 16 outputs; lane l loads ONE x value; taps via
// __shfl_sync; 2 threads/output (h=0: d=0,2,4,6; h=1: d=1,3,5,7); shfl_xor
// combine; no smem/barriers; interior chunks drop boundary predicates.

#define BX_F    1024
#define BX_OPB  128         // outputs per block (8 warps x 16 outputs)
#define BX_TPB  256
#define BX_DEG  8           // polynomial degree (9 coefficients)

// ---------- compile-time math (double precision) ----------
constexpr double BX_LN2 = 0.6931471805599453;
constexpr double BX_PI  = 3.14159265358979323846;

constexpr double bx_cexp(double x) {
    int n = (int)(x / BX_LN2 + (x >= 0.0 ? 0.5 : -0.5));
    double r = x - n * BX_LN2;
    double s = 1.0, term = 1.0;
    for (int k = 1; k <= 12; ++k) { term *= r / k; s += term; }
    double p = 1.0;
    int m = n < 0 ? -n : n;
    if (m > 1100) return n < 0 ? 0.0 : 1e308;
    for (int i = 0; i < m; ++i) p *= 2.0;
    return n < 0 ? s / p : s * p;
}
constexpr double bx_clog1p(double z) {          // z in (0, 1]
    double w = z / (z + 2.0);
    double w2 = w * w, s = 0.0, t = w;
    for (int k = 1; k <= 15; k += 2) { s += t / k; t *= w2; }
    return 2.0 * s;
}
constexpr double bx_csoftplus(double t) {
    double z = bx_cexp(t < 0.0 ? t : -t);
    double l = bx_clog1p(z);
    return (t > 0.0 ? t : 0.0) + l;
}
constexpr double bx_ccos(double x) {            // |x| <= pi
    double x2 = x * x, s = 1.0, t = 1.0;
    for (int k = 1; k <= 24; ++k) { t *= -x2 / ((2.0*k - 1.0) * (2.0*k)); s += t; }
    return s;
}
constexpr double bx_cmask_arg(double arg) {     // 1 - gg(arg), exact formula
    double u = bx_csoftplus(arg);        if (u < 1e-6) u = 1e-6;
    double v = bx_csoftplus(1.0 - arg);  if (v < 1e-6) v = 1e-6;
    double f1 = bx_cexp(-1.0 / u);
    double f2 = bx_cexp(-1.0 / v);
    if (f1 + f2 == 0.0) return 0.0;
    return f2 / (f1 + f2);
}
constexpr double bx_cmask_da(int d, double a) {
    double arg = ((double)(d * d) - a * a) / (6.0 * a + 9.0);
    return bx_cmask_arg(arg);
}

// Deg-BX_DEG Chebyshev interpolation of w_d * mask_d(a) in s = 2a-1,
// Lagrange -> monomial (double); then pair-pack per (h, chain).
struct BxPkH { unsigned long long cA[BX_DEG + 1]; unsigned long long cB[BX_DEG + 1]; };
struct BxPk2 { BxPkH h[2]; };

constexpr BxPk2 bx_make_tabs() {
    double C[8][BX_DEG + 1] = {};
    for (int d = 0; d < 8; ++d) {
        double sj[BX_DEG + 1] = {};
        double yj[BX_DEG + 1] = {};
        for (int j = 0; j <= BX_DEG; ++j) {
            double th = BX_PI * (2.0 * j + 1.0) / (2.0 * (BX_DEG + 1));
            double sz = bx_ccos(th);                // node in [-1,1]
            double a  = 0.5 * (sz + 1.0);           // a in [0,1]
            sj[j] = sz;
            double w = (d == 0) ? 0.5 : 1.0;        // bake d=0 half weight
            yj[j] = w * bx_cmask_da(d, a);
        }
        for (int j = 0; j <= BX_DEG; ++j) {
            double num[BX_DEG + 2] = {};
            num[0] = 1.0;
            int deg = 0;
            double den = 1.0;
            for (int k = 0; k <= BX_DEG; ++k) {
                if (k == j) continue;
                double r = sj[k];
                for (int i = deg + 1; i >= 1; --i) num[i] = num[i - 1] - r * num[i];
                num[0] = -r * num[0];
                ++deg;
                den *= (sj[j] - r);
            }
            double scale = yj[j] / den;
            for (int i = 0; i <= BX_DEG; ++i) C[d][i] += scale * num[i];
        }
    }
    BxPk2 T{};
    for (int h = 0; h < 2; ++h) {
        for (int i = 0; i <= BX_DEG; ++i) {
            // chain A: (d=h, d=h+2)  -> (lo, hi) ; chain B: (d=h+4, d=h+6)
            unsigned int a0 = __builtin_bit_cast(unsigned int, (float)C[h][i]);
            unsigned int a1 = __builtin_bit_cast(unsigned int, (float)C[h + 2][i]);
            unsigned int b0 = __builtin_bit_cast(unsigned int, (float)C[h + 4][i]);
            unsigned int b1 = __builtin_bit_cast(unsigned int, (float)C[h + 6][i]);
            T.h[h].cA[i] = ((unsigned long long)a1 << 32) | a0;
            T.h[h].cB[i] = ((unsigned long long)b1 << 32) | b0;
        }
    }
    return T;
}

__constant__ BxPk2 bx_tabs = bx_make_tabs();

// ---------- runtime ----------
__device__ __forceinline__ float bx_rcp(float x) {
    float r; asm("rcp.approx.ftz.f32 %0, %1;" : "=f"(r) : "f"(x)); return r;
}
__device__ __forceinline__ unsigned long long bx_pack2(float lo, float hi) {
    unsigned long long r;
    asm("mov.b64 %0, {%1, %2};" : "=l"(r)
        : "r"(__float_as_uint(lo)), "r"(__float_as_uint(hi)));
    return r;
}
__device__ __forceinline__ void bx_unpack2(unsigned long long v, float& lo, float& hi) {
    unsigned int a, b;
    asm("mov.b64 {%0, %1}, %2;" : "=r"(a), "=r"(b) : "l"(v));
    lo = __uint_as_float(a);
    hi = __uint_as_float(b);
}
__device__ __forceinline__ unsigned long long bx_fma2(unsigned long long a,
                                                      unsigned long long b,
                                                      unsigned long long c) {
    unsigned long long r;
    asm("fma.rn.f32x2 %0, %1, %2, %3;" : "=l"(r) : "l"(a), "l"(b), "l"(c));
    return r;
}

template <bool INTERIOR>
__device__ __forceinline__ void bx_body(const float* __restrict__ x,
                                        const float* __restrict__ aa,
                                        float* __restrict__ out,
                                        int row, int fbase)
{
    const int warp = (int)threadIdx.x >> 5;       // 0..7
    const int lane = (int)threadIdx.x & 31;
    const int o    = lane >> 1;                   // output within warp: 0..15
    const int h    = lane & 1;                    // tap-parity half

    const int fw = fbase + warp * 16;             // warp's first output
    const int f  = fw + o;

    const float* xr = x + row * BX_F;

    // one x load per lane covers the warp's whole window [fw-8, fw+23]
    float xv;
    {
        const int g = fw - 8 + lane;
        if (INTERIOR) {
            xv = __ldg(xr + g);
        } else {
            xv = (g >= 0 && g < BX_F) ? __ldg(xr + g) : 0.0f;
        }
    }

    const float a = __ldg(aa + row * BX_F + f);
    const float s = fmaf(2.0f, a, -1.0f);         // normalize to [-1,1)
    const unsigned long long ss = bx_pack2(s, s);

    // two packed deg-8 Horner chains: A=(d=h, d=h+2), B=(d=h+4, d=h+6)
    const BxPkH* T = &bx_tabs.h[h];
    unsigned long long pA = T->cA[BX_DEG];
    unsigned long long pB = T->cB[BX_DEG];
    #pragma unroll
    for (int i = BX_DEG - 1; i >= 0; --i) {
        pA = bx_fma2(pA, ss, T->cA[i]);
        pB = bx_fma2(pB, ss, T->cB[i]);
    }

    // weighted masks (d=0 half-weight baked into coefficients)
    float mw[4];
    bx_unpack2(pA, mw[0], mw[1]);
    bx_unpack2(pB, mw[2], mw[3]);

    float ws = 0.0f;
    float dn = 0.0f;

    // h==0: d = 0,2,4,6 ; h==1: d = 1,3,5,7
    #pragma unroll
    for (int k = 0; k < 4; ++k) {
        const int d = 2 * k + h;

        // taps via register shuffle: lane (o +- d) + 8 holds x[f +- d]
        const float xm = __shfl_sync(0xFFFFFFFFu, xv, (o - d) + 8);
        const float xp = __shfl_sync(0xFFFFFFFFu, xv, (o + d) + 8);

        ws = fmaf(mw[k], xm + xp, ws);
        if (INTERIOR) {
            dn += mw[k];
        } else {
            const float cnt = (float)((f >= d) + (f + d < BX_F));
            dn = fmaf(mw[k], cnt, dn);
        }
    }

    float den = INTERIOR ? (dn + dn) : dn;

    // combine tap-parity halves
    ws  += __shfl_xor_sync(0xFFFFFFFFu, ws,  1);
    den += __shfl_xor_sync(0xFFFFFFFFu, den, 1);

    if (h == 0)
        out[row * BX_F + f] = ws * bx_rcp(den);
}

__global__ __launch_bounds__(BX_TPB)
void BumpX_kernel(const float* __restrict__ x,
                  const float* __restrict__ aa,
                  float* __restrict__ out)
{
    const int row   = blockIdx.x >> 3;            // b*L + l
    const int chunk = blockIdx.x & 7;
    const int fbase = chunk * BX_OPB;

    if (chunk != 0 && chunk != 7)
        bx_body<true>(x, aa, out, row, fbase);
    else
        bx_body<false>(x, aa, out, row, fbase);
}

extern "C" void kernel_launch(void* const* d_in, const int* in_sizes, int n_in,
                              void* d_out, int out_size)
{
    const float* x  = (const float*)d_in[0];
    const float* aa = (const float*)d_in[1];
    float* out      = (float*)d_out;

    const int rows = out_size / BX_F;             // B*L = 128
    dim3 grid(rows * (BX_F / BX_OPB));            // 1024 blocks
    BumpX_kernel<<<grid, BX_TPB>>>(x, aa, out);
}

// round 16
// speedup vs baseline: 1.2500x; 1.2500x over previous
#include <cuda_runtime.h>
#include <cuda_bf16.h>

// BumpX: out[b,l,f] = sum_g mask(g-f, aa[b,l,f]) * x[b,l,g] / sum_g mask(...)
// mask(d,a) = 1 - gg(arg), arg = (d^2 - a^2)/(6a+9).
//
// Round 16: R13 skeleton (best: warp-coalesced x load + shuffle taps, shared
// compile-time poly of the tanh pre-activation, warp-UNIFORM literal
// coefficients -> immediate/c-bank FFMA, no LDC (R15's divergent-LDC trap)).
// Changes vs R13:
//   * degree 10 -> 9 (pre-activation error only matters where |p| <~ 4;
//     tanh saturates elsewhere)  -> fewer FMAs.
//   * even/odd Horner split: p(z) = E(z^2) + z*O(z^2), E/O 4-FMA deep ->
//     serial poly depth ~40 -> ~24 cyc; 4 masks/thread = 8 independent
//     4-deep chains (ILP) at the same issue cost.
//   * d=0 half-weight folded into the tanh epilogue constants.
// Math: mask = 0.5 - 0.5*tanh(p(arg)), p = 0.5*(1/v - 1/u),
//   u = clamp(softplus(arg),1e-6), v = clamp(softplus(1-arg),1e-6);
//   p interpolated at deg-9 Chebyshev nodes on arg in [-0.07, 5.45]
//   (constexpr double, exact reference formula incl. clamps).
//   tanh saturates to exactly +-1 -> mask exactly 0/1 (fp32-ref overflow).
//   |d|<=7 window: dropped taps have mask <= 4e-11.
// Structure: warp owns 16 outputs; lane l loads ONE x value; taps via
// __shfl_sync; 2 threads/output (h=0: d=0,2,4,6; h=1: d=1,3,5,7); shfl_xor
// combine; no smem/barriers; interior chunks drop boundary predicates.

#define BX_F    1024
#define BX_OPB  128         // outputs per block (8 warps x 16 outputs)
#define BX_TPB  256
#define BX_DEG  9

constexpr double BX_ALO = -0.07;
constexpr double BX_AHI =  5.45;

// ---------- compile-time math (double precision) ----------
constexpr double BX_LN2 = 0.6931471805599453;
constexpr double BX_PI  = 3.14159265358979323846;

constexpr double bx_cexp(double x) {
    int n = (int)(x / BX_LN2 + (x >= 0.0 ? 0.5 : -0.5));
    double r = x - n * BX_LN2;
    double s = 1.0, term = 1.0;
    for (int k = 1; k <= 12; ++k) { term *= r / k; s += term; }
    double p = 1.0;
    int m = n < 0 ? -n : n;
    if (m > 1100) return n < 0 ? 0.0 : 1e308;
    for (int i = 0; i < m; ++i) p *= 2.0;
    return n < 0 ? s / p : s * p;
}
constexpr double bx_clog1p(double z) {          // z in (0, 1]
    double w = z / (z + 2.0);
    double w2 = w * w, s = 0.0, t = w;
    for (int k = 1; k <= 15; k += 2) { s += t / k; t *= w2; }
    return 2.0 * s;
}
constexpr double bx_csoftplus(double t) {
    double z = bx_cexp(t < 0.0 ? t : -t);
    double l = bx_clog1p(z);
    return (t > 0.0 ? t : 0.0) + l;
}
constexpr double bx_ccos(double x) {            // |x| <= pi
    double x2 = x * x, s = 1.0, t = 1.0;
    for (int k = 1; k <= 24; ++k) { t *= -x2 / ((2.0*k - 1.0) * (2.0*k)); s += t; }
    return s;
}
constexpr double bx_cp(double arg) {            // tanh pre-activation, exact
    double u = bx_csoftplus(arg);        if (u < 1e-6) u = 1e-6;
    double v = bx_csoftplus(1.0 - arg);  if (v < 1e-6) v = 1e-6;
    return 0.5 * (1.0 / v - 1.0 / u);
}

struct BxPoly { float c[BX_DEG + 1]; };

constexpr BxPoly bx_make_poly() {
    constexpr double mid  = 0.5 * (BX_AHI + BX_ALO);
    constexpr double half = 0.5 * (BX_AHI - BX_ALO);
    double zj[BX_DEG + 1] = {};
    double yj[BX_DEG + 1] = {};
    for (int j = 0; j <= BX_DEG; ++j) {
        double th = BX_PI * (2.0 * j + 1.0) / (2.0 * (BX_DEG + 1));
        zj[j] = bx_ccos(th);
        yj[j] = bx_cp(mid + half * zj[j]);
    }
    double C[BX_DEG + 1] = {};
    for (int j = 0; j <= BX_DEG; ++j) {
        double num[BX_DEG + 2] = {};
        num[0] = 1.0;
        int deg = 0;
        double den = 1.0;
        for (int k = 0; k <= BX_DEG; ++k) {
            if (k == j) continue;
            double r = zj[k];
            for (int i = deg + 1; i >= 1; --i) num[i] = num[i - 1] - r * num[i];
            num[0] = -r * num[0];
            ++deg;
            den *= (zj[j] - r);
        }
        double scale = yj[j] / den;
        for (int i = 0; i <= BX_DEG; ++i) C[i] += scale * num[i];
    }
    BxPoly P{};
    for (int i = 0; i <= BX_DEG; ++i) P.c[i] = (float)C[i];
    return P;
}

__constant__ BxPoly bx_poly = bx_make_poly();   // warp-uniform -> c-bank FFMA

// z = arg * BX_ZS1 + BX_ZS0  (normalize to [-1,1])
#define BX_ZS1 (float)(2.0 / (BX_AHI - BX_ALO))
#define BX_ZS0 (float)(-(BX_AHI + BX_ALO) / (BX_AHI - BX_ALO))

// ---------- runtime ----------
__device__ __forceinline__ float bx_rcp(float x) {
    float r; asm("rcp.approx.ftz.f32 %0, %1;" : "=f"(r) : "f"(x)); return r;
}
__device__ __forceinline__ float bx_tanh(float x) {
    float r; asm("tanh.approx.f32 %0, %1;" : "=f"(r) : "f"(x)); return r;
}

// p(z) via even/odd split: two 4-deep FMA chains + combine (deg 9)
__device__ __forceinline__ float bx_p(float z) {
    const float w = z * z;
    float E = bx_poly.c[8];                   // c0 + c2 w + c4 w^2 + c6 w^3 + c8 w^4
    E = fmaf(E, w, bx_poly.c[6]);
    E = fmaf(E, w, bx_poly.c[4]);
    E = fmaf(E, w, bx_poly.c[2]);
    E = fmaf(E, w, bx_poly.c[0]);
    float O = bx_poly.c[9];                   // c1 + c3 w + c5 w^2 + c7 w^3 + c9 w^4
    O = fmaf(O, w, bx_poly.c[7]);
    O = fmaf(O, w, bx_poly.c[5]);
    O = fmaf(O, w, bx_poly.c[3]);
    O = fmaf(O, w, bx_poly.c[1]);
    return fmaf(z, O, E);
}

template <bool INTERIOR>
__device__ __forceinline__ void bx_body(const float* __restrict__ x,
                                        const float* __restrict__ aa,
                                        float* __restrict__ out,
                                        int row, int fbase)
{
    const int warp = (int)threadIdx.x >> 5;       // 0..7
    const int lane = (int)threadIdx.x & 31;
    const int o    = lane >> 1;                   // output within warp: 0..15
    const int h    = lane & 1;                    // tap-parity half

    const int fw = fbase + warp * 16;             // warp's first output
    const int f  = fw + o;

    const float* xr = x + row * BX_F;

    // one x load per lane covers the warp's whole window [fw-8, fw+23]
    float xv;
    {
        const int g = fw - 8 + lane;
        if (INTERIOR) {
            xv = __ldg(xr + g);
        } else {
            xv = (g >= 0 && g < BX_F) ? __ldg(xr + g) : 0.0f;
        }
    }

    const float a = __ldg(aa + row * BX_F + f);

    // z(d) = d^2 * id2 + c0n   (normalized poly argument)
    const float id2 = BX_ZS1 * bx_rcp(fmaf(6.0f, a, 9.0f));
    const float c0n = fmaf(-a * a, id2, BX_ZS0);

    // 4 pre-activations: 8 independent 4-deep FMA chains
    float p[4];
    #pragma unroll
    for (int k = 0; k < 4; ++k) {
        const int d = 2 * k + h;
        p[k] = bx_p(fmaf((float)(d * d), id2, c0n));
    }

    float ws = 0.0f;
    float dn = 0.0f;

    // h==0: d = 0,2,4,6 (d=0 half-weight folded into tanh epilogue);
    // h==1: d = 1,3,5,7
    #pragma unroll
    for (int k = 0; k < 4; ++k) {
        const int   d  = 2 * k + h;
        const float c  = (d == 0) ? 0.25f : 0.5f;           // w * 0.5
        const float mw = fmaf(-c, bx_tanh(p[k]), c);        // w * mask

        // taps via register shuffle: lane (o +- d) + 8 holds x[f +- d]
        const float xm = __shfl_sync(0xFFFFFFFFu, xv, (o - d) + 8);
        const float xp = __shfl_sync(0xFFFFFFFFu, xv, (o + d) + 8);

        ws = fmaf(mw, xm + xp, ws);
        if (INTERIOR) {
            dn += mw;
        } else {
            const float cnt = (float)((f >= d) + (f + d < BX_F));
            dn = fmaf(mw, cnt, dn);
        }
    }

    float den = INTERIOR ? (dn + dn) : dn;

    // combine tap-parity halves
    ws  += __shfl_xor_sync(0xFFFFFFFFu, ws,  1);
    den += __shfl_xor_sync(0xFFFFFFFFu, den, 1);

    if (h == 0)
        out[row * BX_F + f] = ws * bx_rcp(den);
}

__global__ __launch_bounds__(BX_TPB)
void BumpX_kernel(const float* __restrict__ x,
                  const float* __restrict__ aa,
                  float* __restrict__ out)
{
    const int row   = blockIdx.x >> 3;            // b*L + l
    const int chunk = blockIdx.x & 7;
    const int fbase = chunk * BX_OPB;

    if (chunk != 0 && chunk != 7)
        bx_body<true>(x, aa, out, row, fbase);
    else
        bx_body<false>(x, aa, out, row, fbase);
}

extern "C" void kernel_launch(void* const* d_in, const int* in_sizes, int n_in,
                              void* d_out, int out_size)
{
    const float* x  = (const float*)d_in[0];
    const float* aa = (const float*)d_in[1];
    float* out      = (float*)d_out;

    const int rows = out_size / BX_F;             // B*L = 128
    dim3 grid(rows * (BX_F / BX_OPB));            // 1024 blocks
    BumpX_kernel<<<grid, BX_TPB>>>(x, aa, out);
}